// round 3
// baseline (speedup 1.0000x reference)
#include <cuda_runtime.h>
#include <cuda_bf16.h>

#define NN 4096
#define DD 128
#define NBLK 128
#define NTHR 512
#define NWARP (NTHR / 32)
#define REGC 0.05f
#define EPSC 1e-8f
#define NITER 100
#define MUNU (1.0f / 4096.0f)
#define PELEMS ((size_t)NN * NN)          // 16777216 elements per problem
#define SMEM_BYTES (3 * NN * 4 + 256)

// Scratch (__device__ globals — sanctioned, no runtime allocation)
__device__ float g_K32[3 * PELEMS];            // exact K, DRAM-streamed (phase 4)
__device__ __nv_bfloat16 g_Kb [3 * PELEMS];    // bf16 K row-major  (row pass)
__device__ __nv_bfloat16 g_KbT[3 * PELEMS];    // bf16 K col-major  (col pass)
__device__ float g_u[3 * NN];
__device__ float g_v[3 * NN];
__device__ float g_nsq[3 * NN];                // row norms of z0,z1,z2
__device__ double g_loss;
__device__ unsigned int g_bar_count;
__device__ volatile unsigned int g_bar_gen;

__device__ __forceinline__ float bf_lo(unsigned int u) { return __uint_as_float(u << 16); }
__device__ __forceinline__ float bf_hi(unsigned int u) { return __uint_as_float(u & 0xffff0000u); }

// Software grid barrier (128 CTAs, 1/SM, guaranteed co-resident).
// __threadfence() = gpu scope => CCTL.IVALL on sm_103a => cross-CTA visibility.
__device__ __forceinline__ void grid_barrier() {
    __syncthreads();
    if (threadIdx.x == 0) {
        __threadfence();
        unsigned int gen = g_bar_gen;
        if (atomicAdd(&g_bar_count, 1u) == (unsigned)(NBLK - 1)) {
            g_bar_count = 0;
            __threadfence();
            g_bar_gen = gen + 1;
        } else {
            while (g_bar_gen == gen) { }
        }
        __threadfence();
    }
    __syncthreads();
}

// Batched half-step: for each problem p, out[p][r] = MUNU/(dot(M_p[r,:], in[p]) + EPS)
// M = bf16 base covering 3 problems. 6 dot streams per warp (2 rows x 3 problems).
__device__ __forceinline__ void half_step3(
    const __nv_bfloat16* __restrict__ M,
    const float* __restrict__ in_g,
    float* __restrict__ out_g,
    float* s_mem, int tid, int bid, int wid, int lane)
{
    #pragma unroll 4
    for (int i = tid; i < 3 * NN; i += NTHR) s_mem[i] = in_g[i];
    __syncthreads();

    const int row0 = (bid << 5) + (wid << 1);
    const float4* s4 = (const float4*)s_mem;     // [3][1024] float4

    const uint2* k00 = (const uint2*)(M + (size_t)(row0    ) * NN);
    const uint2* k01 = (const uint2*)(M + (size_t)(row0 + 1) * NN);
    const uint2* k10 = (const uint2*)(M + PELEMS     + (size_t)(row0    ) * NN);
    const uint2* k11 = (const uint2*)(M + PELEMS     + (size_t)(row0 + 1) * NN);
    const uint2* k20 = (const uint2*)(M + 2 * PELEMS + (size_t)(row0    ) * NN);
    const uint2* k21 = (const uint2*)(M + 2 * PELEMS + (size_t)(row0 + 1) * NN);

    float a00 = 0.f, a01 = 0.f, a10 = 0.f, a11 = 0.f, a20 = 0.f, a21 = 0.f;

    #pragma unroll 4
    for (int j = lane; j < NN / 4; j += 32) {
        float4 v0 = s4[j];
        float4 v1 = s4[1024 + j];
        float4 v2 = s4[2048 + j];
        uint2 q;
        q = k00[j];
        a00 += bf_lo(q.x) * v0.x + bf_hi(q.x) * v0.y + bf_lo(q.y) * v0.z + bf_hi(q.y) * v0.w;
        q = k01[j];
        a01 += bf_lo(q.x) * v0.x + bf_hi(q.x) * v0.y + bf_lo(q.y) * v0.z + bf_hi(q.y) * v0.w;
        q = k10[j];
        a10 += bf_lo(q.x) * v1.x + bf_hi(q.x) * v1.y + bf_lo(q.y) * v1.z + bf_hi(q.y) * v1.w;
        q = k11[j];
        a11 += bf_lo(q.x) * v1.x + bf_hi(q.x) * v1.y + bf_lo(q.y) * v1.z + bf_hi(q.y) * v1.w;
        q = k20[j];
        a20 += bf_lo(q.x) * v2.x + bf_hi(q.x) * v2.y + bf_lo(q.y) * v2.z + bf_hi(q.y) * v2.w;
        q = k21[j];
        a21 += bf_lo(q.x) * v2.x + bf_hi(q.x) * v2.y + bf_lo(q.y) * v2.z + bf_hi(q.y) * v2.w;
    }

    #pragma unroll
    for (int o = 16; o; o >>= 1) {
        a00 += __shfl_xor_sync(0xffffffffu, a00, o);
        a01 += __shfl_xor_sync(0xffffffffu, a01, o);
        a10 += __shfl_xor_sync(0xffffffffu, a10, o);
        a11 += __shfl_xor_sync(0xffffffffu, a11, o);
        a20 += __shfl_xor_sync(0xffffffffu, a20, o);
        a21 += __shfl_xor_sync(0xffffffffu, a21, o);
    }
    if (lane == 0) {
        out_g[row0]              = MUNU / (a00 + EPSC);
        out_g[row0 + 1]          = MUNU / (a01 + EPSC);
        out_g[NN + row0]         = MUNU / (a10 + EPSC);
        out_g[NN + row0 + 1]     = MUNU / (a11 + EPSC);
        out_g[2 * NN + row0]     = MUNU / (a20 + EPSC);
        out_g[2 * NN + row0 + 1] = MUNU / (a21 + EPSC);
    }
}

__global__ __launch_bounds__(NTHR, 1) void ot_kernel(
    const float* __restrict__ z0, const float* __restrict__ z1,
    const float* __restrict__ z2, float* __restrict__ out)
{
    extern __shared__ __align__(16) float s_mem[];          // 3*4096 floats
    double* s_dacc = (double*)(s_mem + 3 * NN);             // 16 doubles

    const int tid  = threadIdx.x;
    const int bid  = blockIdx.x;
    const int wid  = tid >> 5;
    const int lane = tid & 31;

    if (bid == 0 && tid == 0) g_loss = 0.0;   // reset each graph replay

    const float* Z[3] = { z0, z1, z2 };
    const int XI[3] = { 0, 0, 1 };
    const int YI[3] = { 1, 2, 2 };

    // ---------- Phase 1: row norms of all 3 inputs + u init ----------
    {
        int gw = bid * NWARP + wid;
        for (int r = gw; r < 3 * NN; r += NBLK * NWARP) {
            const float* src = Z[r >> 12];
            int row = r & (NN - 1);
            const float4* rp = (const float4*)(src + (size_t)row * DD);
            float4 v4 = rp[lane];
            float s = v4.x * v4.x + v4.y * v4.y + v4.z * v4.z + v4.w * v4.w;
            #pragma unroll
            for (int o = 16; o; o >>= 1) s += __shfl_xor_sync(0xffffffffu, s, o);
            if (lane == 0) g_nsq[r] = s;
        }
        for (int i = bid * NTHR + tid; i < 3 * NN; i += NBLK * NTHR) g_u[i] = 1.0f;
    }
    grid_barrier();

    // ---------- Phase 2: build K = exp(-C/REG) for all 3 pairs ----------
    {
        float* sxT = s_mem;                 // [32 k][128 i], stride 132
        float* syT = s_mem + 32 * 132;      // [32 k][64  j], stride 68
        const int ty = tid >> 4;            // 0..31
        const int tx = tid & 15;            // 0..15
        const int NT = 3 * (NN / 128) * (NN / 64);   // 6144 tiles

        for (int t = bid; t < NT; t += NBLK) {
            const int p  = t >> 11;
            const int tt = t & 2047;
            const int r0 = (tt >> 6) * 128;
            const int c0 = (tt & 63) * 64;
            const float* x = Z[XI[p]];
            const float* y = Z[YI[p]];
            const float* xsq = g_nsq + XI[p] * NN;
            const float* ysq = g_nsq + YI[p] * NN;
            float* K32 = g_K32 + p * PELEMS;
            __nv_bfloat16* Kb  = g_Kb  + p * PELEMS;
            __nv_bfloat16* KbT = g_KbT + p * PELEMS;

            float acc[4][4];
            #pragma unroll
            for (int m = 0; m < 4; ++m)
                #pragma unroll
                for (int n = 0; n < 4; ++n) acc[m][n] = 0.f;

            for (int kc = 0; kc < DD; kc += 32) {
                __syncthreads();
                #pragma unroll
                for (int idx = tid; idx < 128 * 32; idx += NTHR) {
                    int rr = idx >> 5, cc = idx & 31;
                    sxT[cc * 132 + rr] = x[(size_t)(r0 + rr) * DD + kc + cc];
                }
                #pragma unroll
                for (int idx = tid; idx < 64 * 32; idx += NTHR) {
                    int rr = idx >> 5, cc = idx & 31;
                    syT[cc * 68 + rr] = y[(size_t)(c0 + rr) * DD + kc + cc];
                }
                __syncthreads();
                #pragma unroll 8
                for (int k = 0; k < 32; ++k) {
                    float4 a4 = *(const float4*)&sxT[k * 132 + ty * 4];
                    float4 b4 = *(const float4*)&syT[k * 68 + tx * 4];
                    acc[0][0] += a4.x * b4.x; acc[0][1] += a4.x * b4.y;
                    acc[0][2] += a4.x * b4.z; acc[0][3] += a4.x * b4.w;
                    acc[1][0] += a4.y * b4.x; acc[1][1] += a4.y * b4.y;
                    acc[1][2] += a4.y * b4.z; acc[1][3] += a4.y * b4.w;
                    acc[2][0] += a4.z * b4.x; acc[2][1] += a4.z * b4.y;
                    acc[2][2] += a4.z * b4.z; acc[2][3] += a4.z * b4.w;
                    acc[3][0] += a4.w * b4.x; acc[3][1] += a4.w * b4.y;
                    acc[3][2] += a4.w * b4.z; acc[3][3] += a4.w * b4.w;
                }
            }

            const int j0 = c0 + tx * 4;
            const int i0 = r0 + ty * 4;
            float e[4][4];
            #pragma unroll
            for (int m = 0; m < 4; ++m) {
                float xs = xsq[i0 + m];
                #pragma unroll
                for (int n = 0; n < 4; ++n) {
                    float C = fmaxf(xs + ysq[j0 + n] - 2.f * acc[m][n], 0.f);
                    e[m][n] = __expf(-C * (1.0f / REGC));
                }
                float4 o4 = make_float4(e[m][0], e[m][1], e[m][2], e[m][3]);
                __stcs((float4*)(K32 + (size_t)(i0 + m) * NN + j0), o4);
                __nv_bfloat162 b01 = __floats2bfloat162_rn(e[m][0], e[m][1]);
                __nv_bfloat162 b23 = __floats2bfloat162_rn(e[m][2], e[m][3]);
                uint2 pk;
                pk.x = *(unsigned int*)&b01;
                pk.y = *(unsigned int*)&b23;
                *(uint2*)(Kb + (size_t)(i0 + m) * NN + j0) = pk;
            }
            #pragma unroll
            for (int n = 0; n < 4; ++n) {
                __nv_bfloat162 b01 = __floats2bfloat162_rn(e[0][n], e[1][n]);
                __nv_bfloat162 b23 = __floats2bfloat162_rn(e[2][n], e[3][n]);
                uint2 pk;
                pk.x = *(unsigned int*)&b01;
                pk.y = *(unsigned int*)&b23;
                *(uint2*)(KbT + (size_t)(j0 + n) * NN + i0) = pk;
            }
        }
    }
    grid_barrier();

    // ---------- Phase 3: 100 lock-step Sinkhorn iterations for all 3 ----------
    for (int it = 0; it < NITER; ++it) {
        half_step3(g_KbT, g_u, g_v, s_mem, tid, bid, wid, lane);   // v = nu/(K^T u)
        grid_barrier();
        half_step3(g_Kb, g_v, g_u, s_mem, tid, bid, wid, lane);    // u = mu/(K v)
        grid_barrier();
    }

    // ---------- Phase 4: loss = sum_p sum u K v * (-REG ln K), exact K32 ----------
    {
        #pragma unroll 4
        for (int i = tid; i < 3 * NN; i += NTHR) s_mem[i] = g_v[i];
        __syncthreads();
        const int row0 = (bid << 5) + (wid << 1);
        double wacc = 0.0;
        #pragma unroll
        for (int p = 0; p < 3; ++p) {
            const float4* v4 = (const float4*)(s_mem + p * NN);
            #pragma unroll
            for (int r = 0; r < 2; ++r) {
                int row = row0 + r;
                const float4* kp4 = (const float4*)(g_K32 + p * PELEMS + (size_t)row * NN);
                float acc = 0.f;
                #pragma unroll 4
                for (int j = lane; j < NN / 4; j += 32) {
                    float4 kk = __ldcs(kp4 + j);
                    float4 vv = v4[j];
                    acc += kk.x * vv.x * __logf(kk.x);
                    acc += kk.y * vv.y * __logf(kk.y);
                    acc += kk.z * vv.z * __logf(kk.z);
                    acc += kk.w * vv.w * __logf(kk.w);
                }
                #pragma unroll
                for (int o = 16; o; o >>= 1) acc += __shfl_xor_sync(0xffffffffu, acc, o);
                if (lane == 0) wacc += (double)g_u[p * NN + row] * (double)acc;
            }
        }
        if (lane == 0) s_dacc[wid] = wacc;
        __syncthreads();
        if (tid == 0) {
            double c = 0.0;
            for (int w = 0; w < NWARP; ++w) c += s_dacc[w];
            atomicAdd(&g_loss, (double)(-REGC) * c);
        }
    }
    grid_barrier();

    if (bid == 0 && tid == 0) out[0] = (float)(g_loss / 3.0);
}

extern "C" void kernel_launch(void* const* d_in, const int* in_sizes, int n_in,
                              void* d_out, int out_size) {
    (void)in_sizes; (void)n_in; (void)out_size;
    const float* z0 = (const float*)d_in[0];
    const float* z1 = (const float*)d_in[1];
    const float* z2 = (const float*)d_in[2];
    cudaFuncSetAttribute(ot_kernel, cudaFuncAttributeMaxDynamicSharedMemorySize, SMEM_BYTES);
    ot_kernel<<<NBLK, NTHR, SMEM_BYTES>>>(z0, z1, z2, (float*)d_out);
}

// round 4
// speedup vs baseline: 1.1200x; 1.1200x over previous
#include <cuda_runtime.h>
#include <cuda_bf16.h>

#define NN 4096
#define DD 128
#define NBLK 148
#define NTHR 512
#define NWARP (NTHR / 32)
#define NWTOT (NBLK * NWARP)        // 2368 warps total
#define REGC 0.05f
#define EPSC 1e-8f
#define NITER 100
#define MUNU (1.0f / 4096.0f)

// Scratch (__device__ globals — sanctioned, no runtime allocation)
__device__ float g_K32[(size_t)NN * NN];           // exact K, DRAM-streamed (phase 4)
__device__ __nv_bfloat16 g_Kb [(size_t)NN * NN];   // bf16 K row-major  (row pass)
__device__ __nv_bfloat16 g_KbT[(size_t)NN * NN];   // bf16 K col-major  (col pass)
__device__ float g_u[NN];
__device__ float g_v[NN];
__device__ float g_nsq[3 * NN];
__device__ double g_loss;
__device__ unsigned int g_flags[NBLK * 64];        // one 256B-strided slot per CTA
__device__ volatile unsigned int g_bar_gen;

__device__ __forceinline__ float bf_lo(unsigned int u) { return __uint_as_float(u << 16); }
__device__ __forceinline__ float bf_hi(unsigned int u) { return __uint_as_float(u & 0xffff0000u); }

// One-writer-per-slot grid barrier. Monotonic generations survive graph replays.
// __threadfence() (gpu scope -> CCTL.IVALL) provides release on arrival and
// acquire (L1 invalidate) on departure.
__device__ __forceinline__ void grid_barrier(unsigned int& gen, int tid, int bid) {
    __syncthreads();
    ++gen;
    if (bid == 0) {
        if (tid == 0) {
            __threadfence();
            *(volatile unsigned int*)&g_flags[0] = gen;
        }
        if (tid < NBLK) {
            volatile unsigned int* f = &g_flags[tid * 64];
            while ((int)(*f - gen) < 0) { }
        }
        __syncthreads();                 // all 148 slots observed
        if (tid == 0) {
            __threadfence();             // acquire for CTA0 + order release store
            g_bar_gen = gen;
        }
        __syncthreads();
    } else {
        if (tid == 0) {
            __threadfence();             // release my CTA's writes
            *(volatile unsigned int*)&g_flags[bid * 64] = gen;
            while ((int)(g_bar_gen - gen) < 0) { }
            __threadfence();             // acquire (invalidate stale L1)
        }
        __syncthreads();
    }
}

// Half-step: out[r] = MUNU / (dot(M[r,:], in_s) + EPS) for this warp's 1-2 rows.
__device__ __forceinline__ void half_step(
    const __nv_bfloat16* __restrict__ M,
    const float* __restrict__ in_g,
    float* __restrict__ out_g,
    float* s_mem, int tid, int lane, int w_begin, int w_end)
{
    {
        float4* s4w = (float4*)s_mem;
        const float4* g4 = (const float4*)in_g;
        #pragma unroll
        for (int i = tid; i < NN / 4; i += NTHR) s4w[i] = g4[i];
    }
    __syncthreads();

    const float4* s4 = (const float4*)s_mem;
    const int row0 = w_begin;
    const bool two = (w_begin + 2 <= w_end);

    if (two) {
        const uint2* k0 = (const uint2*)(M + (size_t)row0 * NN);
        const uint2* k1 = (const uint2*)(M + (size_t)(row0 + 1) * NN);
        float a0 = 0.f, a1 = 0.f;
        #pragma unroll 8
        for (int j = lane; j < NN / 4; j += 32) {
            float4 vv = s4[j];
            uint2 p0 = k0[j];
            uint2 p1 = k1[j];
            a0 += bf_lo(p0.x) * vv.x + bf_hi(p0.x) * vv.y
                + bf_lo(p0.y) * vv.z + bf_hi(p0.y) * vv.w;
            a1 += bf_lo(p1.x) * vv.x + bf_hi(p1.x) * vv.y
                + bf_lo(p1.y) * vv.z + bf_hi(p1.y) * vv.w;
        }
        #pragma unroll
        for (int o = 16; o; o >>= 1) {
            a0 += __shfl_xor_sync(0xffffffffu, a0, o);
            a1 += __shfl_xor_sync(0xffffffffu, a1, o);
        }
        if (lane == 0) {
            out_g[row0]     = MUNU / (a0 + EPSC);
            out_g[row0 + 1] = MUNU / (a1 + EPSC);
        }
    } else {
        const uint2* k0 = (const uint2*)(M + (size_t)row0 * NN);
        float a0 = 0.f;
        #pragma unroll 8
        for (int j = lane; j < NN / 4; j += 32) {
            float4 vv = s4[j];
            uint2 p0 = k0[j];
            a0 += bf_lo(p0.x) * vv.x + bf_hi(p0.x) * vv.y
                + bf_lo(p0.y) * vv.z + bf_hi(p0.y) * vv.w;
        }
        #pragma unroll
        for (int o = 16; o; o >>= 1) a0 += __shfl_xor_sync(0xffffffffu, a0, o);
        if (lane == 0) out_g[row0] = MUNU / (a0 + EPSC);
    }
    __syncthreads();   // s_mem reused next half-step
}

__global__ __launch_bounds__(NTHR, 1) void ot_kernel(
    const float* __restrict__ z0, const float* __restrict__ z1,
    const float* __restrict__ z2, float* __restrict__ out)
{
    __shared__ __align__(16) float s_mem[6400];
    __shared__ double s_dacc[NWARP];

    const int tid  = threadIdx.x;
    const int bid  = blockIdx.x;
    const int wid  = tid >> 5;
    const int lane = tid & 31;
    const int gw   = bid * NWARP + wid;
    // Per-warp row range for pass phases: 1 or 2 rows, exact cover of [0,NN)
    const int w_begin = (int)(((long long)gw * NN) / NWTOT);
    const int w_end   = (int)(((long long)(gw + 1) * NN) / NWTOT);

    unsigned int gen = g_bar_gen;        // monotonic across graph replays

    if (bid == 0 && tid == 0) g_loss = 0.0;

    const float* Z[3] = { z0, z1, z2 };
    const int XI[3] = { 0, 0, 1 };
    const int YI[3] = { 1, 2, 2 };

    // ---------- Phase 0 (once): row norms of z0,z1,z2 ----------
    for (int r = bid * NWARP + wid; r < 3 * NN; r += NBLK * NWARP) {
        const float* src = Z[r >> 12];
        int row = r & (NN - 1);
        const float4* rp = (const float4*)(src + (size_t)row * DD);
        float4 v4 = rp[lane];
        float s = v4.x * v4.x + v4.y * v4.y + v4.z * v4.z + v4.w * v4.w;
        #pragma unroll
        for (int o = 16; o; o >>= 1) s += __shfl_xor_sync(0xffffffffu, s, o);
        if (lane == 0) g_nsq[r] = s;
    }
    grid_barrier(gen, tid, bid);

    for (int p = 0; p < 3; ++p) {
        const float* x = Z[XI[p]];
        const float* y = Z[YI[p]];
        const float* xsq = g_nsq + XI[p] * NN;
        const float* ysq = g_nsq + YI[p] * NN;

        // ---------- Phase 2: build K = exp(-C/REG); write K32/Kb/KbT; init u ----------
        {
            for (int i = bid * NTHR + tid; i < NN; i += NBLK * NTHR) g_u[i] = 1.0f;

            float* sxT = s_mem;                 // [32 k][128 i], stride 132
            float* syT = s_mem + 32 * 132;      // [32 k][64  j], stride 68
            const int ty = tid >> 4;
            const int tx = tid & 15;
            const int NT = (NN / 128) * (NN / 64);   // 2048 tiles

            for (int t = bid; t < NT; t += NBLK) {
                const int r0 = (t >> 6) * 128;
                const int c0 = (t & 63) * 64;
                float acc[4][4];
                #pragma unroll
                for (int m = 0; m < 4; ++m)
                    #pragma unroll
                    for (int n = 0; n < 4; ++n) acc[m][n] = 0.f;

                for (int kc = 0; kc < DD; kc += 32) {
                    __syncthreads();
                    #pragma unroll
                    for (int idx = tid; idx < 128 * 32; idx += NTHR) {
                        int rr = idx >> 5, cc = idx & 31;
                        sxT[cc * 132 + rr] = x[(size_t)(r0 + rr) * DD + kc + cc];
                    }
                    #pragma unroll
                    for (int idx = tid; idx < 64 * 32; idx += NTHR) {
                        int rr = idx >> 5, cc = idx & 31;
                        syT[cc * 68 + rr] = y[(size_t)(c0 + rr) * DD + kc + cc];
                    }
                    __syncthreads();
                    #pragma unroll 8
                    for (int k = 0; k < 32; ++k) {
                        float4 a4 = *(const float4*)&sxT[k * 132 + ty * 4];
                        float4 b4 = *(const float4*)&syT[k * 68 + tx * 4];
                        acc[0][0] += a4.x * b4.x; acc[0][1] += a4.x * b4.y;
                        acc[0][2] += a4.x * b4.z; acc[0][3] += a4.x * b4.w;
                        acc[1][0] += a4.y * b4.x; acc[1][1] += a4.y * b4.y;
                        acc[1][2] += a4.y * b4.z; acc[1][3] += a4.y * b4.w;
                        acc[2][0] += a4.z * b4.x; acc[2][1] += a4.z * b4.y;
                        acc[2][2] += a4.z * b4.z; acc[2][3] += a4.z * b4.w;
                        acc[3][0] += a4.w * b4.x; acc[3][1] += a4.w * b4.y;
                        acc[3][2] += a4.w * b4.z; acc[3][3] += a4.w * b4.w;
                    }
                }

                const int j0 = c0 + tx * 4;
                const int i0 = r0 + ty * 4;
                float e[4][4];
                #pragma unroll
                for (int m = 0; m < 4; ++m) {
                    float xs = xsq[i0 + m];
                    #pragma unroll
                    for (int n = 0; n < 4; ++n) {
                        float C = fmaxf(xs + ysq[j0 + n] - 2.f * acc[m][n], 0.f);
                        e[m][n] = __expf(-C * (1.0f / REGC));
                    }
                    float4 o4 = make_float4(e[m][0], e[m][1], e[m][2], e[m][3]);
                    __stcs((float4*)(g_K32 + (size_t)(i0 + m) * NN + j0), o4);
                    __nv_bfloat162 b01 = __floats2bfloat162_rn(e[m][0], e[m][1]);
                    __nv_bfloat162 b23 = __floats2bfloat162_rn(e[m][2], e[m][3]);
                    uint2 pk;
                    pk.x = *(unsigned int*)&b01;
                    pk.y = *(unsigned int*)&b23;
                    *(uint2*)(g_Kb + (size_t)(i0 + m) * NN + j0) = pk;
                }
                #pragma unroll
                for (int n = 0; n < 4; ++n) {
                    __nv_bfloat162 b01 = __floats2bfloat162_rn(e[0][n], e[1][n]);
                    __nv_bfloat162 b23 = __floats2bfloat162_rn(e[2][n], e[3][n]);
                    uint2 pk;
                    pk.x = *(unsigned int*)&b01;
                    pk.y = *(unsigned int*)&b23;
                    *(uint2*)(g_KbT + (size_t)(j0 + n) * NN + i0) = pk;
                }
            }
        }
        grid_barrier(gen, tid, bid);

        // ---------- Phase 3: 100 Sinkhorn iterations ----------
        for (int it = 0; it < NITER; ++it) {
            half_step(g_KbT, g_u, g_v, s_mem, tid, lane, w_begin, w_end);  // v = nu/(K^T u)
            grid_barrier(gen, tid, bid);
            half_step(g_Kb, g_v, g_u, s_mem, tid, lane, w_begin, w_end);   // u = mu/(K v)
            grid_barrier(gen, tid, bid);
        }

        // ---------- Phase 4: loss += sum u_i K_ij v_j * (-REG ln K_ij) (exact K32) ----------
        {
            {
                float4* s4w = (float4*)s_mem;
                const float4* g4 = (const float4*)g_v;
                #pragma unroll
                for (int i = tid; i < NN / 4; i += NTHR) s4w[i] = g4[i];
            }
            __syncthreads();
            const float4* v4 = (const float4*)s_mem;
            double wacc = 0.0;
            for (int row = w_begin; row < w_end; ++row) {
                const float4* kp4 = (const float4*)(g_K32 + (size_t)row * NN);
                float acc = 0.f;
                #pragma unroll 4
                for (int j = lane; j < NN / 4; j += 32) {
                    float4 kk = __ldcs(kp4 + j);
                    float4 vv = v4[j];
                    acc += kk.x * vv.x * __logf(kk.x);
                    acc += kk.y * vv.y * __logf(kk.y);
                    acc += kk.z * vv.z * __logf(kk.z);
                    acc += kk.w * vv.w * __logf(kk.w);
                }
                #pragma unroll
                for (int o = 16; o; o >>= 1) acc += __shfl_xor_sync(0xffffffffu, acc, o);
                if (lane == 0) wacc += (double)g_u[row] * (double)acc;
            }
            if (lane == 0) s_dacc[wid] = wacc;
            __syncthreads();
            if (tid == 0) {
                double c = 0.0;
                for (int w = 0; w < NWARP; ++w) c += s_dacc[w];
                atomicAdd(&g_loss, (double)(-REGC) * c);
            }
        }
        grid_barrier(gen, tid, bid);   // loss done + protect K before next pair
    }

    if (bid == 0 && tid == 0) out[0] = (float)(g_loss / 3.0);
}

extern "C" void kernel_launch(void* const* d_in, const int* in_sizes, int n_in,
                              void* d_out, int out_size) {
    (void)in_sizes; (void)n_in; (void)out_size;
    const float* z0 = (const float*)d_in[0];
    const float* z1 = (const float*)d_in[1];
    const float* z2 = (const float*)d_in[2];
    ot_kernel<<<NBLK, NTHR>>>(z0, z1, z2, (float*)d_out);
}

// round 5
// speedup vs baseline: 1.1377x; 1.0158x over previous
#include <cuda_runtime.h>
#include <cuda_bf16.h>

#define NN 4096
#define DD 128
#define NBLK 148
#define NTHR 1024
#define NWARP (NTHR / 32)
#define REGC 0.05f
#define EPSC 1e-8f
#define NITER 100
#define MUNU (1.0f / 4096.0f)

// Scratch (__device__ globals — sanctioned)
__device__ __nv_bfloat16 g_Kb [(size_t)NN * NN];   // bf16 K row-major  (row pass)
__device__ __nv_bfloat16 g_KbT[(size_t)NN * NN];   // bf16 K col-major  (col pass)
__device__ float g_u[NN];
__device__ float g_v[NN];
__device__ float g_nsq[3 * NN];
__device__ double g_loss;
__device__ unsigned int g_flags[NBLK * 64];        // 256B-strided slot per CTA
__device__ unsigned int g_bar_gen;

__device__ __forceinline__ float bf_lo(unsigned int u) { return __uint_as_float(u << 16); }
__device__ __forceinline__ float bf_hi(unsigned int u) { return __uint_as_float(u & 0xffff0000u); }

__device__ __forceinline__ unsigned int ld_acq(const unsigned int* p) {
    unsigned int v;
    asm volatile("ld.acquire.gpu.global.u32 %0, [%1];" : "=r"(v) : "l"(p) : "memory");
    return v;
}
__device__ __forceinline__ void st_rel(unsigned int* p, unsigned int v) {
    asm volatile("st.release.gpu.global.u32 [%0], %1;" :: "l"(p), "r"(v) : "memory");
}

// Fence-free grid barrier: release/acquire only, no CCTL.IVALL.
// All cross-barrier shared data is read with __ldcg (L2) or is write-once (K).
__device__ __forceinline__ void grid_barrier(unsigned int& gen, int tid, int bid) {
    __syncthreads();
    ++gen;
    if (bid == 0) {
        if (tid == 0) st_rel(&g_flags[0], gen);
        if (tid > 0 && tid < NBLK) {
            const unsigned int* f = &g_flags[tid * 64];
            while ((int)(ld_acq(f) - gen) < 0) { }
        }
        __syncthreads();                       // all 148 arrivals observed+acquired
        if (tid == 0) st_rel(&g_bar_gen, gen);
    } else {
        if (tid == 0) {
            st_rel(&g_flags[bid * 64], gen);
            while ((int)(ld_acq(&g_bar_gen) - gen) < 0) { }
        }
        __syncthreads();
    }
}

__device__ __forceinline__ float dot8(uint4 q, float4 va, float4 vb, float acc) {
    acc += bf_lo(q.x) * va.x + bf_hi(q.x) * va.y
         + bf_lo(q.y) * va.z + bf_hi(q.y) * va.w
         + bf_lo(q.z) * vb.x + bf_hi(q.z) * vb.y
         + bf_lo(q.w) * vb.z + bf_hi(q.w) * vb.w;
    return acc;
}

// Half-step: out[r] = MUNU / (dot(M[r,:], in) + EPS) for this CTA's rows [rb,re).
// Warp w: row pair p = w>>1 (2 rows), j-half = w&1 (2048 cols). Partial sums
// combined through s_part.
__device__ __forceinline__ void half_step(
    const __nv_bfloat16* __restrict__ M,
    const float* __restrict__ in_g,
    float* __restrict__ out_g,
    float* s_vec, float* s_part,
    int rb, int re, int tid, int wid, int lane)
{
    ((float4*)s_vec)[tid] = __ldcg(((const float4*)in_g) + tid);   // 1024*16B = 16KB
    __syncthreads();

    const int nrows = re - rb;
    const int p  = wid >> 1;
    const int jh = wid & 1;
    const int r0 = rb + 2 * p;
    const bool v0r = (2 * p     < nrows);
    const bool v1r = (2 * p + 1 < nrows);

    float a0 = 0.f, a1 = 0.f;
    if (v0r) {
        const uint4* k0 = (const uint4*)(M + (size_t)r0 * NN + jh * 2048);
        const float4* v4 = (const float4*)s_vec + jh * 512;
        if (v1r) {
            const uint4* k1 = (const uint4*)(M + (size_t)(r0 + 1) * NN + jh * 2048);
            #pragma unroll 4
            for (int k = 0; k < 8; ++k) {
                int pos = lane + 32 * k;            // 0..255
                uint4 q0 = k0[pos];
                uint4 q1 = k1[pos];
                float4 va = v4[2 * pos];
                float4 vb = v4[2 * pos + 1];
                a0 = dot8(q0, va, vb, a0);
                a1 = dot8(q1, va, vb, a1);
            }
        } else {
            #pragma unroll 4
            for (int k = 0; k < 8; ++k) {
                int pos = lane + 32 * k;
                uint4 q0 = k0[pos];
                float4 va = v4[2 * pos];
                float4 vb = v4[2 * pos + 1];
                a0 = dot8(q0, va, vb, a0);
            }
        }
    }
    #pragma unroll
    for (int o = 16; o; o >>= 1) {
        a0 += __shfl_xor_sync(0xffffffffu, a0, o);
        a1 += __shfl_xor_sync(0xffffffffu, a1, o);
    }
    if (lane == 0 && v0r) {
        s_part[(2 * p) * 2 + jh] = a0;
        if (v1r) s_part[(2 * p + 1) * 2 + jh] = a1;
    }
    __syncthreads();
    if (tid < nrows) {
        float s = s_part[tid * 2] + s_part[tid * 2 + 1];
        out_g[rb + tid] = MUNU / (s + EPSC);
    }
}

__global__ __launch_bounds__(NTHR, 1) void ot_kernel(
    const float* __restrict__ z0, const float* __restrict__ z1,
    const float* __restrict__ z2, float* __restrict__ out)
{
    // GEMM: sxT[32][132] + syT[32][132] = 33,792 B. Passes: s_vec(16KB)+s_part.
    __shared__ __align__(16) float s_mem[2 * 32 * 132];
    __shared__ float s_part[64];
    __shared__ double s_dval[64];

    const int tid  = threadIdx.x;
    const int bid  = blockIdx.x;
    const int wid  = tid >> 5;
    const int lane = tid & 31;
    // This CTA's output-row range (27 or 28 rows)
    const int rb = (int)(((long long)bid * NN) / NBLK);
    const int re = (int)(((long long)(bid + 1) * NN) / NBLK);

    unsigned int gen = g_bar_gen;            // monotonic across graph replays

    if (bid == 0 && tid == 0) g_loss = 0.0;

    const float* Z[3] = { z0, z1, z2 };
    const int XI[3] = { 0, 0, 1 };
    const int YI[3] = { 1, 2, 2 };

    // ---------- Phase 0 (once): row norms of z0,z1,z2 ----------
    for (int r = bid * NWARP + wid; r < 3 * NN; r += NBLK * NWARP) {
        const float* src = Z[r >> 12];
        int row = r & (NN - 1);
        float4 v4 = ((const float4*)(src + (size_t)row * DD))[lane];
        float s = v4.x * v4.x + v4.y * v4.y + v4.z * v4.z + v4.w * v4.w;
        #pragma unroll
        for (int o = 16; o; o >>= 1) s += __shfl_xor_sync(0xffffffffu, s, o);
        if (lane == 0) g_nsq[r] = s;
    }
    grid_barrier(gen, tid, bid);

    for (int pr = 0; pr < 3; ++pr) {
        const float* x = Z[XI[pr]];
        const float* y = Z[YI[pr]];
        const float* xsq = g_nsq + XI[pr] * NN;
        const float* ysq = g_nsq + YI[pr] * NN;

        // ---------- Phase 2: K = exp(-C/REG) -> Kb, KbT; init u ----------
        {
            for (int i = bid * NTHR + tid; i < NN; i += NBLK * NTHR) g_u[i] = 1.0f;

            float* sxT = s_mem;                  // [32 k][128 i], stride 132
            float* syT = s_mem + 32 * 132;       // [32 k][128 j], stride 132
            const int ty = tid >> 5;             // 0..31
            const int tx = tid & 31;             // 0..31
            const int NT = (NN / 128) * (NN / 128);   // 1024 tiles of 128x128

            for (int t = bid; t < NT; t += NBLK) {
                const int r0 = (t >> 5) * 128;
                const int c0 = (t & 31) * 128;
                float acc[4][4];
                #pragma unroll
                for (int m = 0; m < 4; ++m)
                    #pragma unroll
                    for (int n = 0; n < 4; ++n) acc[m][n] = 0.f;

                for (int kc = 0; kc < DD; kc += 32) {
                    __syncthreads();
                    #pragma unroll
                    for (int idx = tid; idx < 128 * 32; idx += NTHR) {
                        int rr = idx >> 5, cc = idx & 31;
                        sxT[cc * 132 + rr] = x[(size_t)(r0 + rr) * DD + kc + cc];
                        syT[cc * 132 + rr] = y[(size_t)(c0 + rr) * DD + kc + cc];
                    }
                    __syncthreads();
                    #pragma unroll 8
                    for (int k = 0; k < 32; ++k) {
                        float4 a4 = *(const float4*)&sxT[k * 132 + ty * 4];
                        float4 b4 = *(const float4*)&syT[k * 132 + tx * 4];
                        acc[0][0] += a4.x * b4.x; acc[0][1] += a4.x * b4.y;
                        acc[0][2] += a4.x * b4.z; acc[0][3] += a4.x * b4.w;
                        acc[1][0] += a4.y * b4.x; acc[1][1] += a4.y * b4.y;
                        acc[1][2] += a4.y * b4.z; acc[1][3] += a4.y * b4.w;
                        acc[2][0] += a4.z * b4.x; acc[2][1] += a4.z * b4.y;
                        acc[2][2] += a4.z * b4.z; acc[2][3] += a4.z * b4.w;
                        acc[3][0] += a4.w * b4.x; acc[3][1] += a4.w * b4.y;
                        acc[3][2] += a4.w * b4.z; acc[3][3] += a4.w * b4.w;
                    }
                }

                const int j0 = c0 + tx * 4;
                const int i0 = r0 + ty * 4;
                float e[4][4];
                #pragma unroll
                for (int m = 0; m < 4; ++m) {
                    float xs = __ldcg(&xsq[i0 + m]);
                    #pragma unroll
                    for (int n = 0; n < 4; ++n) {
                        float C = fmaxf(xs + __ldcg(&ysq[j0 + n]) - 2.f * acc[m][n], 0.f);
                        e[m][n] = __expf(-C * (1.0f / REGC));
                    }
                    __nv_bfloat162 b01 = __floats2bfloat162_rn(e[m][0], e[m][1]);
                    __nv_bfloat162 b23 = __floats2bfloat162_rn(e[m][2], e[m][3]);
                    uint2 pk;
                    pk.x = *(unsigned int*)&b01;
                    pk.y = *(unsigned int*)&b23;
                    *(uint2*)(g_Kb + (size_t)(i0 + m) * NN + j0) = pk;
                }
                #pragma unroll
                for (int n = 0; n < 4; ++n) {
                    __nv_bfloat162 b01 = __floats2bfloat162_rn(e[0][n], e[1][n]);
                    __nv_bfloat162 b23 = __floats2bfloat162_rn(e[2][n], e[3][n]);
                    uint2 pk;
                    pk.x = *(unsigned int*)&b01;
                    pk.y = *(unsigned int*)&b23;
                    *(uint2*)(g_KbT + (size_t)(j0 + n) * NN + i0) = pk;
                }
            }
        }
        grid_barrier(gen, tid, bid);

        // ---------- Phase 3: 100 Sinkhorn iterations ----------
        for (int it = 0; it < NITER; ++it) {
            half_step(g_KbT, g_u, g_v, s_mem, s_part, rb, re, tid, wid, lane);  // v
            grid_barrier(gen, tid, bid);
            half_step(g_Kb, g_v, g_u, s_mem, s_part, rb, re, tid, wid, lane);   // u
            grid_barrier(gen, tid, bid);
        }

        // ---------- Phase 4: loss += sum u_i Kb_ij v_j * (-REG * ln Kb_ij) ----------
        {
            ((float4*)s_mem)[tid] = __ldcg(((const float4*)g_v) + tid);
            __syncthreads();
            const int nrows = re - rb;
            const int p  = wid >> 1;
            const int jh = wid & 1;
            const int r0 = rb + 2 * p;
            const bool v0r = (2 * p     < nrows);
            const bool v1r = (2 * p + 1 < nrows);
            float a0 = 0.f, a1 = 0.f;
            if (v0r) {
                const float4* v4 = (const float4*)s_mem + jh * 512;
                for (int rr = 0; rr < (v1r ? 2 : 1); ++rr) {
                    const uint4* kr = (const uint4*)(g_Kb + (size_t)(r0 + rr) * NN + jh * 2048);
                    float acc = 0.f;
                    #pragma unroll 2
                    for (int k = 0; k < 8; ++k) {
                        int pos = lane + 32 * k;
                        uint4 q = kr[pos];
                        float4 va = v4[2 * pos];
                        float4 vb = v4[2 * pos + 1];
                        float f;
                        f = bf_lo(q.x); acc += f * va.x * __logf(f);
                        f = bf_hi(q.x); acc += f * va.y * __logf(f);
                        f = bf_lo(q.y); acc += f * va.z * __logf(f);
                        f = bf_hi(q.y); acc += f * va.w * __logf(f);
                        f = bf_lo(q.z); acc += f * vb.x * __logf(f);
                        f = bf_hi(q.z); acc += f * vb.y * __logf(f);
                        f = bf_lo(q.w); acc += f * vb.z * __logf(f);
                        f = bf_hi(q.w); acc += f * vb.w * __logf(f);
                    }
                    if (rr == 0) a0 = acc; else a1 = acc;
                }
            }
            #pragma unroll
            for (int o = 16; o; o >>= 1) {
                a0 += __shfl_xor_sync(0xffffffffu, a0, o);
                a1 += __shfl_xor_sync(0xffffffffu, a1, o);
            }
            if (lane == 0 && v0r) {
                s_part[(2 * p) * 2 + jh] = a0;
                if (v1r) s_part[(2 * p + 1) * 2 + jh] = a1;
            }
            __syncthreads();
            if (tid < nrows) {
                float tot = s_part[tid * 2] + s_part[tid * 2 + 1];
                s_dval[tid] = (double)__ldcg(&g_u[rb + tid]) * (double)tot;
            }
            __syncthreads();
            if (tid == 0) {
                double c = 0.0;
                int nrows2 = re - rb;
                for (int i = 0; i < nrows2; ++i) c += s_dval[i];
                atomicAdd(&g_loss, (double)(-REGC) * c);
            }
        }
        grid_barrier(gen, tid, bid);   // loss done + protect K before next pair
    }

    if (bid == 0 && tid == 0) out[0] = (float)(__ldcg(&g_loss) / 3.0);
}

extern "C" void kernel_launch(void* const* d_in, const int* in_sizes, int n_in,
                              void* d_out, int out_size) {
    (void)in_sizes; (void)n_in; (void)out_size;
    const float* z0 = (const float*)d_in[0];
    const float* z1 = (const float*)d_in[1];
    const float* z2 = (const float*)d_in[2];
    ot_kernel<<<NBLK, NTHR>>>(z0, z1, z2, (float*)d_out);
}